// round 16
// baseline (speedup 1.0000x reference)
#include <cuda_runtime.h>
#include <cuda_bf16.h>
#include <cuda_fp16.h>
#include <math.h>
#include <cstdint>

#define B_ 2
#define S_ 2048
#define D_ 4096
#define H_ 32
#define KV_ 8
#define HD_ 128
#define T_ (B_*S_)
#define REP_ (H_/KV_)

// ---------------------------------------------------------------------------
// Scratch (device globals: allocation-free rule)
// ---------------------------------------------------------------------------
__device__ __half g_attn16[T_ * D_];       // attention out (fp16, feeds O-proj)

__device__ __half g_x16[T_ * D_];          // fp16 GEMM operands
__device__ __half g_wq16[D_ * D_];
__device__ __half g_wk16[KV_ * HD_ * D_];
__device__ __half g_wv16[KV_ * HD_ * D_];
__device__ __half g_wo16[D_ * D_];

__device__ __half g_q16[T_ * D_];          // roped + scale*log2e fp16 Q
__device__ __half g_k16[T_ * KV_ * HD_];   // roped fp16 K
__device__ __half g_v16[T_ * KV_ * HD_];   // V fp16

// ---------------------------------------------------------------------------
// Helpers
// ---------------------------------------------------------------------------
__device__ __forceinline__ uint32_t smem_to_u32(const void* smem_ptr) {
    uint32_t addr;
    asm("{ .reg .u64 tmp; cvta.to.shared.u64 tmp, %1; cvt.u32.u64 %0, tmp; }"
        : "=r"(addr) : "l"(smem_ptr));
    return addr;
}
__device__ __forceinline__ void cp_async16(uint32_t saddr, const void* gaddr) {
    asm volatile("cp.async.cg.shared.global [%0], [%1], 16;"
                 :: "r"(saddr), "l"(gaddr));
}
#define CP_COMMIT() asm volatile("cp.async.commit_group;")
#define CP_WAIT(n)  asm volatile("cp.async.wait_group %0;" :: "n"(n))

__device__ __forceinline__ uint32_t lds32(uint32_t addr) {
    uint32_t v;
    asm("ld.shared.b32 %0, [%1];" : "=r"(v) : "r"(addr));
    return v;
}

#define MMA_F16(d, a, bb0, bb1) \
    asm volatile("mma.sync.aligned.m16n8k16.row.col.f32.f16.f16.f32 " \
        "{%0,%1,%2,%3}, {%4,%5,%6,%7}, {%8,%9}, {%0,%1,%2,%3};" \
        : "+f"((d)[0]), "+f"((d)[1]), "+f"((d)[2]), "+f"((d)[3]) \
        : "r"((a)[0]), "r"((a)[1]), "r"((a)[2]), "r"((a)[3]), \
          "r"(bb0), "r"(bb1))

#define LDSM4(d0,d1,d2,d3,a) \
    asm volatile("ldmatrix.sync.aligned.m8n8.x4.shared.b16 {%0,%1,%2,%3}, [%4];" \
        : "=r"(d0), "=r"(d1), "=r"(d2), "=r"(d3) : "r"(a))
#define LDSM4T(d0,d1,d2,d3,a) \
    asm volatile("ldmatrix.sync.aligned.m8n8.x4.trans.shared.b16 {%0,%1,%2,%3}, [%4];" \
        : "=r"(d0), "=r"(d1), "=r"(d2), "=r"(d3) : "r"(a))

__device__ __forceinline__ uint32_t packf16(float lo, float hi) {
    uint32_t r;
    asm("cvt.rn.f16x2.f32 %0, %1, %2;" : "=r"(r) : "f"(hi), "f"(lo));
    return r;
}
__device__ __forceinline__ float ex2f(float x) {
    float r;
    asm("ex2.approx.f32 %0, %1;" : "=f"(r) : "f"(x));
    return r;
}
__device__ __forceinline__ uint32_t ex2h2(uint32_t x) {
    uint32_t r;
    asm("ex2.approx.f16x2 %0, %1;" : "=r"(r) : "r"(x));
    return r;
}

// ---------------------------------------------------------------------------
// fp32 -> fp16 convert (x and weights)
// ---------------------------------------------------------------------------
__global__ void to_f16(const float* __restrict__ X, __half* __restrict__ Y, int n4)
{
    int i = blockIdx.x * blockDim.x + threadIdx.x;
    if (i >= n4) return;
    float4 v = reinterpret_cast<const float4*>(X)[i];
    uint2 o;
    o.x = packf16(v.x, v.y);
    o.y = packf16(v.z, v.w);
    reinterpret_cast<uint2*>(Y)[i] = o;
}

// ---------------------------------------------------------------------------
// fp16 GEMM (R11-winning body) with fused epilogue:
//   mode 0: fp32 out; mode 1: fp16 out; mode 2: RoPE(+scale) + fp16 out.
// blockIdx.z selects (B0,C0,mode0,sc0) / (B1,C1,mode1,sc1).
// ---------------------------------------------------------------------------
#define GT_BYTES 16384
#define GSTAGE (2 * GT_BYTES)
#define GF16_SMEM (2 * GSTAGE)

__device__ __forceinline__ void g16_copy(
    uint32_t sbase, const __half* __restrict__ Ab, const __half* __restrict__ Bb,
    int K, int k0, int tid)
{
    #pragma unroll
    for (int t = 0; t < 2; t++) {
        const __half* src = t ? Bb : Ab;
        uint32_t toff = sbase + t * GT_BYTES;
        #pragma unroll
        for (int p = 0; p < 4; p++) {
            int idx = p * 256 + tid;
            int row = idx >> 3;
            int ch  = idx & 7;
            uint32_t dst = toff + row * 128 +
                           (uint32_t)((ch * 16) ^ ((row & 7) << 4));
            cp_async16(dst, src + (size_t)row * K + k0 + ch * 8);
        }
    }
}

__global__ void __launch_bounds__(256)
gemm_f16(const __half* __restrict__ A,
         const __half* __restrict__ B0, const __half* __restrict__ B1,
         void* __restrict__ C0v, void* __restrict__ C1v,
         int N, int K, int mode0, int mode1, float sc0, float sc1,
         const float* __restrict__ fc, const float* __restrict__ fs)
{
    extern __shared__ __align__(1024) char smem[];
    const uint32_t sb0 = smem_to_u32(smem);
    const int tid  = threadIdx.x;
    const int wid  = tid >> 5;
    const int lane = tid & 31;
    const int bm = blockIdx.y * 128;
    const int bn = blockIdx.x * 128;
    const __half* Bw = blockIdx.z ? B1 : B0;
    void* Cv = blockIdx.z ? C1v : C0v;
    const int mode = blockIdx.z ? mode1 : mode0;
    const float sc = blockIdx.z ? sc1 : sc0;
    const int warp_m = (wid >> 2) * 64;
    const int warp_n = (wid & 3) * 32;
    const int NC = K >> 6;

    const __half* Ab = A  + (size_t)bm * K;
    const __half* Bb = Bw + (size_t)bn * K;

    float acc[4][4][4];
    #pragma unroll
    for (int i = 0; i < 4; i++)
        #pragma unroll
        for (int j = 0; j < 4; j++)
            #pragma unroll
            for (int r = 0; r < 4; r++) acc[i][j][r] = 0.f;

    const int lg  = lane >> 2;
    const int lk4 = (lane & 3) * 4;

    g16_copy(sb0, Ab, Bb, K, 0, tid);
    CP_COMMIT();

    for (int c = 0; c < NC; c++) {
        if (c + 1 < NC) {
            g16_copy(sb0 + ((c + 1) & 1) * GSTAGE, Ab, Bb, K, (c + 1) << 6, tid);
            CP_COMMIT();
            CP_WAIT(1);
        } else {
            CP_WAIT(0);
        }
        __syncthreads();

        const uint32_t sb = sb0 + (c & 1) * GSTAGE;

        #pragma unroll
        for (int ks = 0; ks < 4; ks++) {
            const int kb = ks * 32 + lk4;

            uint32_t ah[4][4], bh[4][2];
            #pragma unroll
            for (int mt = 0; mt < 4; mt++) {
                int r0 = warp_m + mt * 16 + lg;
                int r1 = r0 + 8;
                uint32_t rb0 = r0 * 128, rx0 = (r0 & 7) << 4;
                uint32_t rb1 = r1 * 128, rx1 = (r1 & 7) << 4;
                ah[mt][0] = lds32(sb + rb0 + (kb ^ rx0));
                ah[mt][1] = lds32(sb + rb1 + (kb ^ rx1));
                ah[mt][2] = lds32(sb + rb0 + ((kb + 16) ^ rx0));
                ah[mt][3] = lds32(sb + rb1 + ((kb + 16) ^ rx1));
            }
            #pragma unroll
            for (int nt = 0; nt < 4; nt++) {
                int n = warp_n + nt * 8 + lg;
                uint32_t rb = n * 128, rx = (n & 7) << 4;
                bh[nt][0] = lds32(sb + GT_BYTES + rb + (kb ^ rx));
                bh[nt][1] = lds32(sb + GT_BYTES + rb + ((kb + 16) ^ rx));
            }
            #pragma unroll
            for (int mt = 0; mt < 4; mt++)
                #pragma unroll
                for (int nt = 0; nt < 4; nt++)
                    MMA_F16(acc[mt][nt], ah[mt], bh[nt][0], bh[nt][1]);
        }
        __syncthreads();
    }

    if (mode == 0) {
        float* C = (float*)Cv;
        #pragma unroll
        for (int mt = 0; mt < 4; mt++) {
            int row = bm + warp_m + mt * 16 + lg;
            #pragma unroll
            for (int nt = 0; nt < 4; nt++) {
                int col = bn + warp_n + nt * 8 + (lane & 3) * 2;
                *(float2*)(C + (size_t)row * N + col) =
                    make_float2(acc[mt][nt][0], acc[mt][nt][1]);
                *(float2*)(C + (size_t)(row + 8) * N + col) =
                    make_float2(acc[mt][nt][2], acc[mt][nt][3]);
            }
        }
    } else if (mode == 1) {
        __half* C = (__half*)Cv;
        #pragma unroll
        for (int mt = 0; mt < 4; mt++) {
            int row = bm + warp_m + mt * 16 + lg;
            #pragma unroll
            for (int nt = 0; nt < 4; nt++) {
                int col = bn + warp_n + nt * 8 + (lane & 3) * 2;
                *reinterpret_cast<uint32_t*>(C + (size_t)row * N + col) =
                    packf16(acc[mt][nt][0], acc[mt][nt][1]);
                *reinterpret_cast<uint32_t*>(C + (size_t)(row + 8) * N + col) =
                    packf16(acc[mt][nt][2], acc[mt][nt][3]);
            }
        }
    } else {
        // mode 2: fused RoPE(+scale) + fp16. col pairs are rope pairs.
        __half* C = (__half*)Cv;
        #pragma unroll
        for (int mt = 0; mt < 4; mt++) {
            int row = bm + warp_m + mt * 16 + lg;
            int s0 = row & (S_ - 1);
            int s1 = (row + 8) & (S_ - 1);
            #pragma unroll
            for (int nt = 0; nt < 4; nt++) {
                int col = bn + warp_n + nt * 8 + (lane & 3) * 2;
                int i = (col & (HD_ - 1)) >> 1;
                float c0 = fc[s0*64 + i], sn0 = fs[s0*64 + i];
                float c1 = fc[s1*64 + i], sn1 = fs[s1*64 + i];
                float a0 = acc[mt][nt][0], a1 = acc[mt][nt][1];
                float b0 = acc[mt][nt][2], b1 = acc[mt][nt][3];
                *reinterpret_cast<uint32_t*>(C + (size_t)row * N + col) =
                    packf16((a0 * c0 - a1 * sn0) * sc, (a0 * sn0 + a1 * c0) * sc);
                *reinterpret_cast<uint32_t*>(C + (size_t)(row + 8) * N + col) =
                    packf16((b0 * c1 - b1 * sn1) * sc, (b0 * sn1 + b1 * c1) * sc);
            }
        }
    }
}

// ---------------------------------------------------------------------------
// Flash attention v16: K-tile 64, 96KB smem -> 2 CTAs/SM (16 warps: cross-CTA
// latency hiding for softmax/LDSM phases). QK fp16 single-pass (log2 scores),
// ex2.approx.f16x2 softmax (output = fp16 P frags), ones-MMA l-sum,
// PV fp16 single-pass, fp16 epilogue.
// ---------------------------------------------------------------------------
#define FQ16 (128 * 256)              // Q fp16: 32KB
#define FK16 (64 * 256)               // K fp16: 16KB
#define FV16 (64 * 256)               // V fp16: 16KB
#define FST16 (FK16 + FV16)           // 32KB per stage
#define FA16_SMEM (FQ16 + 2 * FST16)  // 98304

__device__ __forceinline__ void fa16_load_kv(
    uint32_t sbase, const __half* __restrict__ K16,
    const __half* __restrict__ V16, int tk0, int g, int tid)
{
    const __half* srcs[2] = {K16 + (size_t)tk0 * (KV_*HD_) + g * HD_,
                             V16 + (size_t)tk0 * (KV_*HD_) + g * HD_};
    #pragma unroll
    for (int t = 0; t < 2; t++) {
        #pragma unroll
        for (int it = 0; it < 4; it++) {
            int idx = it * 256 + tid;
            int row = idx >> 4, ch = idx & 15;
            uint32_t dst = sbase + t * FK16 + row * 256 +
                           (uint32_t)((ch * 16) ^ ((row & 7) << 4));
            cp_async16(dst, srcs[t] + (size_t)row * (KV_*HD_) + ch * 8);
        }
    }
}

__global__ void __launch_bounds__(256, 2)
flash_v16(const __half* __restrict__ Q16, const __half* __restrict__ K16,
          const __half* __restrict__ V16, __half* __restrict__ Og)
{
    extern __shared__ __align__(1024) char fsm[];
    const uint32_t sb = smem_to_u32(fsm);
    const int tid  = threadIdx.x;
    const int wid  = tid >> 5;
    const int lane = tid & 31;
    const int qt = (gridDim.x - 1) - blockIdx.x;   // heavy tiles first
    const int h  = blockIdx.y;
    const int b  = blockIdx.z;
    const int g  = h / REP_;
    const int q0 = qt * 128;
    const int t0 = b * S_ + q0;
    const int nt = 2 * qt + 2;                     // 64-key tiles

    const int l7    = lane & 7;
    const int lb8   = (lane >> 3) & 1;
    const int lhi16 = (lane >= 16) ? 16 : 0;
    const int qrow  = 16 * wid + l7 + lb8 * 8;
    const uint32_t qswz = (uint32_t)(l7 << 4);
    const int krow_l = l7 + ((lane >= 16) ? 8 : 0);
    const int kgsel  = lb8 * 16;
    const uint32_t kswz = (uint32_t)(l7 << 4);
    const int vrow_l = l7 + lb8 * 8;
    const int vgsel  = lhi16;
    const uint32_t vswz = (uint32_t)(l7 << 4);
    const uint32_t ONESH2 = 0x3C003C00u;           // (1.0h, 1.0h)

    fa16_load_kv(sb + FQ16, K16, V16, b * S_, g, tid);
    CP_COMMIT();
    {   // stage Q (fp16, 128 rows x 256B)
        const __half* src = Q16 + (size_t)t0 * D_ + h * HD_;
        #pragma unroll
        for (int it = 0; it < 8; it++) {
            int idx = it * 256 + tid;
            int row = idx >> 4, ch = idx & 15;
            uint32_t dst = sb + row * 256 + (uint32_t)((ch * 16) ^ ((row & 7) << 4));
            cp_async16(dst, src + (size_t)row * D_ + ch * 8);
        }
        CP_COMMIT();
    }

    float o[16][4];
    #pragma unroll
    for (int f = 0; f < 16; f++)
        #pragma unroll
        for (int r = 0; r < 4; r++) o[f][r] = 0.f;
    float m0 = -1e30f, m1 = -1e30f;
    float lsum0 = 0.f, lsum1 = 0.f;   // full row sums via ones-MMA

    const int r0g = q0 + 16 * wid + (lane >> 2);
    const int c0l = (lane & 3) * 2;

    for (int t = 0; t < nt; t++) {
        CP_WAIT(0);
        __syncthreads();
        if (t + 1 < nt) {
            fa16_load_kv(sb + FQ16 + ((t + 1) & 1) * FST16,
                         K16, V16, b * S_ + (t + 1) * 64, g, tid);
            CP_COMMIT();
        }

        const uint32_t kb  = sb + FQ16 + (t & 1) * FST16;
        const uint32_t vb  = kb + FK16;

        float s[8][4];
        #pragma unroll
        for (int j = 0; j < 8; j++)
            #pragma unroll
            for (int r = 0; r < 4; r++) s[j][r] = 0.f;

        // ---- S = Q K^T (fp16 single pass; log2-domain scores) ----
        #pragma unroll
        for (int kk = 0; kk < 8; kk++) {
            uint32_t qh[4];
            uint32_t qa = sb + qrow * 256 + (uint32_t)(((kk * 32) + lhi16) ^ qswz);
            LDSM4(qh[0], qh[1], qh[2], qh[3], qa);
            #pragma unroll
            for (int np = 0; np < 4; np++) {
                uint32_t ka = kb + (np * 16 + krow_l) * 256 +
                              (uint32_t)(((kk * 32) + kgsel) ^ kswz);
                uint32_t b0, b1, b2, b3;
                LDSM4(b0, b1, b2, b3, ka);
                MMA_F16(s[2*np],   qh, b0, b1);
                MMA_F16(s[2*np+1], qh, b2, b3);
            }
        }

        if (t >= 2 * qt) {   // diagonal region: causal mask
            const int k0 = t * 64;
            #pragma unroll
            for (int j = 0; j < 8; j++) {
                int cg = k0 + 8 * j + c0l;
                if (cg     > r0g)     s[j][0] = -1e30f;
                if (cg + 1 > r0g)     s[j][1] = -1e30f;
                if (cg     > r0g + 8) s[j][2] = -1e30f;
                if (cg + 1 > r0g + 8) s[j][3] = -1e30f;
            }
        }

        // ---- online softmax (log2 domain, f16x2 MUFU) ----
        float rm0 = -1e30f, rm1 = -1e30f;
        #pragma unroll
        for (int j = 0; j < 8; j++) {
            rm0 = fmaxf(rm0, fmaxf(s[j][0], s[j][1]));
            rm1 = fmaxf(rm1, fmaxf(s[j][2], s[j][3]));
        }
        rm0 = fmaxf(rm0, __shfl_xor_sync(0xffffffffu, rm0, 1));
        rm0 = fmaxf(rm0, __shfl_xor_sync(0xffffffffu, rm0, 2));
        rm1 = fmaxf(rm1, __shfl_xor_sync(0xffffffffu, rm1, 1));
        rm1 = fmaxf(rm1, __shfl_xor_sync(0xffffffffu, rm1, 2));
        float mn0 = fmaxf(m0, rm0), mn1 = fmaxf(m1, rm1);
        float a0 = ex2f(m0 - mn0), a1 = ex2f(m1 - mn1);
        m0 = mn0; m1 = mn1;

        #pragma unroll
        for (int j = 0; j < 8; j++) {
            uint32_t e01 = ex2h2(packf16(s[j][0] - mn0, s[j][1] - mn0));
            uint32_t e23 = ex2h2(packf16(s[j][2] - mn1, s[j][3] - mn1));
            s[j][0] = __uint_as_float(e01);
            s[j][1] = __uint_as_float(e23);
        }

        #pragma unroll
        for (int f = 0; f < 16; f++) {
            o[f][0] *= a0; o[f][1] *= a0;
            o[f][2] *= a1; o[f][3] *= a1;
        }

        // ---- O += P V (fp16) and l += P @ ones ----
        float lacc[4] = {0.f, 0.f, 0.f, 0.f};
        #pragma unroll
        for (int kk = 0; kk < 4; kk++) {
            uint32_t ah[4];
            ah[0] = __float_as_uint(s[2*kk][0]);
            ah[1] = __float_as_uint(s[2*kk][1]);
            ah[2] = __float_as_uint(s[2*kk+1][0]);
            ah[3] = __float_as_uint(s[2*kk+1][1]);
            MMA_F16(lacc, ah, ONESH2, ONESH2);
            #pragma unroll
            for (int dgp = 0; dgp < 8; dgp++) {
                uint32_t va = vb + (kk * 16 + vrow_l) * 256 +
                              (uint32_t)(((dgp * 32) + vgsel) ^ vswz);
                uint32_t b0, b1, b2, b3;
                LDSM4T(b0, b1, b2, b3, va);
                MMA_F16(o[2*dgp],   ah, b0, b1);
                MMA_F16(o[2*dgp+1], ah, b2, b3);
            }
        }
        lsum0 = lsum0 * a0 + lacc[0];
        lsum1 = lsum1 * a1 + lacc[2];
    }

    // epilogue: lsum is the full row sum — no reduction needed
    const float inv0 = 1.0f / lsum0;
    const float inv1 = 1.0f / lsum1;
    const int rowg = t0 + 16 * wid + (lane >> 2);
    #pragma unroll
    for (int dg = 0; dg < 16; dg++) {
        int col = h * HD_ + dg * 8 + (lane & 3) * 2;
        *reinterpret_cast<uint32_t*>(Og + (size_t)rowg * D_ + col) =
            packf16(o[dg][0] * inv0, o[dg][1] * inv0);
        *reinterpret_cast<uint32_t*>(Og + (size_t)(rowg + 8) * D_ + col) =
            packf16(o[dg][2] * inv1, o[dg][3] * inv1);
    }
}

// ---------------------------------------------------------------------------
extern "C" void kernel_launch(void* const* d_in, const int* in_sizes, int n_in,
                              void* d_out, int out_size)
{
    const float* x  = (const float*)d_in[0];
    const float* fc = (const float*)d_in[1];
    const float* fs = (const float*)d_in[2];
    const float* wq = (const float*)d_in[3];
    const float* wk = (const float*)d_in[4];
    const float* wv = (const float*)d_in[5];
    const float* wo = (const float*)d_in[6];
    float* out = (float*)d_out;

    __half *x16, *wq16, *wk16, *wv16, *wo16, *attn16, *q16, *k16, *v16;
    cudaGetSymbolAddress((void**)&x16,  g_x16);
    cudaGetSymbolAddress((void**)&wq16, g_wq16);
    cudaGetSymbolAddress((void**)&wk16, g_wk16);
    cudaGetSymbolAddress((void**)&wv16, g_wv16);
    cudaGetSymbolAddress((void**)&wo16, g_wo16);
    cudaGetSymbolAddress((void**)&attn16, g_attn16);
    cudaGetSymbolAddress((void**)&q16, g_q16);
    cudaGetSymbolAddress((void**)&k16, g_k16);
    cudaGetSymbolAddress((void**)&v16, g_v16);

    cudaFuncSetAttribute(gemm_f16,
                         cudaFuncAttributeMaxDynamicSharedMemorySize, GF16_SMEM);
    cudaFuncSetAttribute(flash_v16,
                         cudaFuncAttributeMaxDynamicSharedMemorySize, FA16_SMEM);

    const int n4_xd = T_ * D_ / 4;
    const int n4_w  = D_ * D_ / 4;
    const int n4_kv = KV_ * HD_ * D_ / 4;
    // 1/sqrt(128) * log2(e): flash softmax runs in log2 domain
    const float qscale = 0.08838834764831845f * 1.4426950408889634f;

    to_f16<<<(n4_xd + 255)/256, 256>>>(x,  x16,  n4_xd);
    to_f16<<<(n4_w  + 255)/256, 256>>>(wq, wq16, n4_w);
    to_f16<<<(n4_kv + 255)/256, 256>>>(wk, wk16, n4_kv);
    to_f16<<<(n4_kv + 255)/256, 256>>>(wv, wv16, n4_kv);
    to_f16<<<(n4_w  + 255)/256, 256>>>(wo, wo16, n4_w);

    dim3 blk(256);
    // Q projection: fused rope+scale, fp16 out
    gemm_f16<<<dim3(D_/128, T_/128, 1), blk, GF16_SMEM>>>(
        x16, wq16, wq16, q16, q16, D_, D_, 2, 2, qscale, qscale, fc, fs);
    // fused K+V projections: z=0 K (rope, sc=1), z=1 V (plain fp16)
    gemm_f16<<<dim3((KV_*HD_)/128, T_/128, 2), blk, GF16_SMEM>>>(
        x16, wk16, wv16, k16, v16, KV_*HD_, D_, 2, 1, 1.0f, 1.0f, fc, fs);

    flash_v16<<<dim3(S_/128, H_, B_), blk, FA16_SMEM>>>(q16, k16, v16, attn16);

    // O projection: fp32 out
    gemm_f16<<<dim3(D_/128, T_/128, 1), blk, GF16_SMEM>>>(
        attn16, wo16, wo16, out, out, D_, D_, 0, 0, 1.0f, 1.0f, fc, fs);
}

// round 17
// speedup vs baseline: 1.1126x; 1.1126x over previous
#include <cuda_runtime.h>
#include <cuda_bf16.h>
#include <cuda_fp16.h>
#include <math.h>
#include <cstdint>

#define B_ 2
#define S_ 2048
#define D_ 4096
#define H_ 32
#define KV_ 8
#define HD_ 128
#define T_ (B_*S_)
#define REP_ (H_/KV_)

// ---------------------------------------------------------------------------
// Scratch (device globals: allocation-free rule)
// ---------------------------------------------------------------------------
__device__ __half g_attn16[T_ * D_];       // attention out (fp16, feeds O-proj)

__device__ __half g_x16[T_ * D_];          // fp16 GEMM operands
__device__ __half g_wq16[D_ * D_];
__device__ __half g_wk16[KV_ * HD_ * D_];
__device__ __half g_wv16[KV_ * HD_ * D_];
__device__ __half g_wo16[D_ * D_];

__device__ __half g_q16[T_ * D_];          // roped + scale*log2e fp16 Q
__device__ __half g_k16[T_ * KV_ * HD_];   // roped fp16 K
__device__ __half g_v16[T_ * KV_ * HD_];   // V fp16

// ---------------------------------------------------------------------------
// Helpers
// ---------------------------------------------------------------------------
__device__ __forceinline__ uint32_t smem_to_u32(const void* smem_ptr) {
    uint32_t addr;
    asm("{ .reg .u64 tmp; cvta.to.shared.u64 tmp, %1; cvt.u32.u64 %0, tmp; }"
        : "=r"(addr) : "l"(smem_ptr));
    return addr;
}
__device__ __forceinline__ void cp_async16(uint32_t saddr, const void* gaddr) {
    asm volatile("cp.async.cg.shared.global [%0], [%1], 16;"
                 :: "r"(saddr), "l"(gaddr));
}
#define CP_COMMIT() asm volatile("cp.async.commit_group;")
#define CP_WAIT(n)  asm volatile("cp.async.wait_group %0;" :: "n"(n))

__device__ __forceinline__ uint32_t lds32(uint32_t addr) {
    uint32_t v;
    asm("ld.shared.b32 %0, [%1];" : "=r"(v) : "r"(addr));
    return v;
}

#define MMA_F16(d, a, bb0, bb1) \
    asm volatile("mma.sync.aligned.m16n8k16.row.col.f32.f16.f16.f32 " \
        "{%0,%1,%2,%3}, {%4,%5,%6,%7}, {%8,%9}, {%0,%1,%2,%3};" \
        : "+f"((d)[0]), "+f"((d)[1]), "+f"((d)[2]), "+f"((d)[3]) \
        : "r"((a)[0]), "r"((a)[1]), "r"((a)[2]), "r"((a)[3]), \
          "r"(bb0), "r"(bb1))

#define LDSM4(d0,d1,d2,d3,a) \
    asm volatile("ldmatrix.sync.aligned.m8n8.x4.shared.b16 {%0,%1,%2,%3}, [%4];" \
        : "=r"(d0), "=r"(d1), "=r"(d2), "=r"(d3) : "r"(a))
#define LDSM4T(d0,d1,d2,d3,a) \
    asm volatile("ldmatrix.sync.aligned.m8n8.x4.trans.shared.b16 {%0,%1,%2,%3}, [%4];" \
        : "=r"(d0), "=r"(d1), "=r"(d2), "=r"(d3) : "r"(a))

__device__ __forceinline__ uint32_t packf16(float lo, float hi) {
    uint32_t r;
    asm("cvt.rn.f16x2.f32 %0, %1, %2;" : "=r"(r) : "f"(hi), "f"(lo));
    return r;
}
__device__ __forceinline__ float ex2f(float x) {
    float r;
    asm("ex2.approx.f32 %0, %1;" : "=f"(r) : "f"(x));
    return r;
}
__device__ __forceinline__ uint32_t ex2h2(uint32_t x) {
    uint32_t r;
    asm("ex2.approx.f16x2 %0, %1;" : "=r"(r) : "r"(x));
    return r;
}

// ---------------------------------------------------------------------------
// fp32 -> fp16 convert (x and weights)
// ---------------------------------------------------------------------------
__global__ void to_f16(const float* __restrict__ X, __half* __restrict__ Y, int n4)
{
    int i = blockIdx.x * blockDim.x + threadIdx.x;
    if (i >= n4) return;
    float4 v = reinterpret_cast<const float4*>(X)[i];
    uint2 o;
    o.x = packf16(v.x, v.y);
    o.y = packf16(v.z, v.w);
    reinterpret_cast<uint2*>(Y)[i] = o;
}

// ---------------------------------------------------------------------------
// fp16 GEMM (R11-winning body) with fused epilogue:
//   mode 0: fp32 out; mode 1: fp16 out; mode 2: RoPE(+scale) + fp16 out.
// blockIdx.z selects (B0,C0,mode0,sc0) / (B1,C1,mode1,sc1).
// ---------------------------------------------------------------------------
#define GT_BYTES 16384
#define GSTAGE (2 * GT_BYTES)
#define GF16_SMEM (2 * GSTAGE)

__device__ __forceinline__ void g16_copy(
    uint32_t sbase, const __half* __restrict__ Ab, const __half* __restrict__ Bb,
    int K, int k0, int tid)
{
    #pragma unroll
    for (int t = 0; t < 2; t++) {
        const __half* src = t ? Bb : Ab;
        uint32_t toff = sbase + t * GT_BYTES;
        #pragma unroll
        for (int p = 0; p < 4; p++) {
            int idx = p * 256 + tid;
            int row = idx >> 3;
            int ch  = idx & 7;
            uint32_t dst = toff + row * 128 +
                           (uint32_t)((ch * 16) ^ ((row & 7) << 4));
            cp_async16(dst, src + (size_t)row * K + k0 + ch * 8);
        }
    }
}

__global__ void __launch_bounds__(256)
gemm_f16(const __half* __restrict__ A,
         const __half* __restrict__ B0, const __half* __restrict__ B1,
         void* __restrict__ C0v, void* __restrict__ C1v,
         int N, int K, int mode0, int mode1, float sc0, float sc1,
         const float* __restrict__ fc, const float* __restrict__ fs)
{
    extern __shared__ __align__(1024) char smem[];
    const uint32_t sb0 = smem_to_u32(smem);
    const int tid  = threadIdx.x;
    const int wid  = tid >> 5;
    const int lane = tid & 31;
    const int bm = blockIdx.y * 128;
    const int bn = blockIdx.x * 128;
    const __half* Bw = blockIdx.z ? B1 : B0;
    void* Cv = blockIdx.z ? C1v : C0v;
    const int mode = blockIdx.z ? mode1 : mode0;
    const float sc = blockIdx.z ? sc1 : sc0;
    const int warp_m = (wid >> 2) * 64;
    const int warp_n = (wid & 3) * 32;
    const int NC = K >> 6;

    const __half* Ab = A  + (size_t)bm * K;
    const __half* Bb = Bw + (size_t)bn * K;

    float acc[4][4][4];
    #pragma unroll
    for (int i = 0; i < 4; i++)
        #pragma unroll
        for (int j = 0; j < 4; j++)
            #pragma unroll
            for (int r = 0; r < 4; r++) acc[i][j][r] = 0.f;

    const int lg  = lane >> 2;
    const int lk4 = (lane & 3) * 4;

    g16_copy(sb0, Ab, Bb, K, 0, tid);
    CP_COMMIT();

    for (int c = 0; c < NC; c++) {
        if (c + 1 < NC) {
            g16_copy(sb0 + ((c + 1) & 1) * GSTAGE, Ab, Bb, K, (c + 1) << 6, tid);
            CP_COMMIT();
            CP_WAIT(1);
        } else {
            CP_WAIT(0);
        }
        __syncthreads();

        const uint32_t sb = sb0 + (c & 1) * GSTAGE;

        #pragma unroll
        for (int ks = 0; ks < 4; ks++) {
            const int kb = ks * 32 + lk4;

            uint32_t ah[4][4], bh[4][2];
            #pragma unroll
            for (int mt = 0; mt < 4; mt++) {
                int r0 = warp_m + mt * 16 + lg;
                int r1 = r0 + 8;
                uint32_t rb0 = r0 * 128, rx0 = (r0 & 7) << 4;
                uint32_t rb1 = r1 * 128, rx1 = (r1 & 7) << 4;
                ah[mt][0] = lds32(sb + rb0 + (kb ^ rx0));
                ah[mt][1] = lds32(sb + rb1 + (kb ^ rx1));
                ah[mt][2] = lds32(sb + rb0 + ((kb + 16) ^ rx0));
                ah[mt][3] = lds32(sb + rb1 + ((kb + 16) ^ rx1));
            }
            #pragma unroll
            for (int nt = 0; nt < 4; nt++) {
                int n = warp_n + nt * 8 + lg;
                uint32_t rb = n * 128, rx = (n & 7) << 4;
                bh[nt][0] = lds32(sb + GT_BYTES + rb + (kb ^ rx));
                bh[nt][1] = lds32(sb + GT_BYTES + rb + ((kb + 16) ^ rx));
            }
            #pragma unroll
            for (int mt = 0; mt < 4; mt++)
                #pragma unroll
                for (int nt = 0; nt < 4; nt++)
                    MMA_F16(acc[mt][nt], ah[mt], bh[nt][0], bh[nt][1]);
        }
        __syncthreads();
    }

    if (mode == 0) {
        float* C = (float*)Cv;
        #pragma unroll
        for (int mt = 0; mt < 4; mt++) {
            int row = bm + warp_m + mt * 16 + lg;
            #pragma unroll
            for (int nt = 0; nt < 4; nt++) {
                int col = bn + warp_n + nt * 8 + (lane & 3) * 2;
                *(float2*)(C + (size_t)row * N + col) =
                    make_float2(acc[mt][nt][0], acc[mt][nt][1]);
                *(float2*)(C + (size_t)(row + 8) * N + col) =
                    make_float2(acc[mt][nt][2], acc[mt][nt][3]);
            }
        }
    } else if (mode == 1) {
        __half* C = (__half*)Cv;
        #pragma unroll
        for (int mt = 0; mt < 4; mt++) {
            int row = bm + warp_m + mt * 16 + lg;
            #pragma unroll
            for (int nt = 0; nt < 4; nt++) {
                int col = bn + warp_n + nt * 8 + (lane & 3) * 2;
                *reinterpret_cast<uint32_t*>(C + (size_t)row * N + col) =
                    packf16(acc[mt][nt][0], acc[mt][nt][1]);
                *reinterpret_cast<uint32_t*>(C + (size_t)(row + 8) * N + col) =
                    packf16(acc[mt][nt][2], acc[mt][nt][3]);
            }
        }
    } else {
        // mode 2: fused RoPE(+scale) + fp16. col pairs are rope pairs.
        __half* C = (__half*)Cv;
        #pragma unroll
        for (int mt = 0; mt < 4; mt++) {
            int row = bm + warp_m + mt * 16 + lg;
            int s0 = row & (S_ - 1);
            int s1 = (row + 8) & (S_ - 1);
            #pragma unroll
            for (int nt = 0; nt < 4; nt++) {
                int col = bn + warp_n + nt * 8 + (lane & 3) * 2;
                int i = (col & (HD_ - 1)) >> 1;
                float c0 = fc[s0*64 + i], sn0 = fs[s0*64 + i];
                float c1 = fc[s1*64 + i], sn1 = fs[s1*64 + i];
                float a0 = acc[mt][nt][0], a1 = acc[mt][nt][1];
                float b0 = acc[mt][nt][2], b1 = acc[mt][nt][3];
                *reinterpret_cast<uint32_t*>(C + (size_t)row * N + col) =
                    packf16((a0 * c0 - a1 * sn0) * sc, (a0 * sn0 + a1 * c0) * sc);
                *reinterpret_cast<uint32_t*>(C + (size_t)(row + 8) * N + col) =
                    packf16((b0 * c1 - b1 * sn1) * sc, (b0 * sn1 + b1 * c1) * sc);
            }
        }
    }
}

// ---------------------------------------------------------------------------
// Flash attention v15 body (R15-measured-best): K-tile 128, 1 CTA/SM,
// QK fp16 single-pass (log2 scores), ex2.approx.f16x2 softmax (output = fp16
// P frags), ones-MMA l-sum, PV fp16 single-pass, fp16 epilogue.
// ---------------------------------------------------------------------------
#define FQ14 (128 * 256)              // Q fp16
#define FK14 (128 * 256)              // K fp16 (128 keys)
#define FV14 (128 * 256)              // V fp16
#define FST14 (FK14 + FV14)           // 64KB per stage
#define FA14_SMEM (FQ14 + 2 * FST14)  // 163840

__device__ __forceinline__ void fa14_load_kv(
    uint32_t sbase, const __half* __restrict__ K16,
    const __half* __restrict__ V16, int tk0, int g, int tid)
{
    const __half* srcs[2] = {K16 + (size_t)tk0 * (KV_*HD_) + g * HD_,
                             V16 + (size_t)tk0 * (KV_*HD_) + g * HD_};
    #pragma unroll
    for (int t = 0; t < 2; t++) {
        #pragma unroll
        for (int it = 0; it < 8; it++) {
            int idx = it * 256 + tid;
            int row = idx >> 4, ch = idx & 15;
            uint32_t dst = sbase + t * FK14 + row * 256 +
                           (uint32_t)((ch * 16) ^ ((row & 7) << 4));
            cp_async16(dst, srcs[t] + (size_t)row * (KV_*HD_) + ch * 8);
        }
    }
}

__global__ void __launch_bounds__(256, 1)
flash_v17(const __half* __restrict__ Q16, const __half* __restrict__ K16,
          const __half* __restrict__ V16, __half* __restrict__ Og)
{
    extern __shared__ __align__(1024) char fsm[];
    const uint32_t sb = smem_to_u32(fsm);
    const int tid  = threadIdx.x;
    const int wid  = tid >> 5;
    const int lane = tid & 31;
    const int qt = (gridDim.x - 1) - blockIdx.x;   // heavy tiles first
    const int h  = blockIdx.y;
    const int b  = blockIdx.z;
    const int g  = h / REP_;
    const int q0 = qt * 128;
    const int t0 = b * S_ + q0;
    const int nt = qt + 1;                         // 128-key tiles

    const int l7    = lane & 7;
    const int lb8   = (lane >> 3) & 1;
    const int lhi16 = (lane >= 16) ? 16 : 0;
    const int qrow  = 16 * wid + l7 + lb8 * 8;
    const uint32_t qswz = (uint32_t)(l7 << 4);
    const int krow_l = l7 + ((lane >= 16) ? 8 : 0);
    const int kgsel  = lb8 * 16;
    const uint32_t kswz = (uint32_t)(l7 << 4);
    const int vrow_l = l7 + lb8 * 8;
    const int vgsel  = lhi16;
    const uint32_t vswz = (uint32_t)(l7 << 4);
    const uint32_t ONESH2 = 0x3C003C00u;           // (1.0h, 1.0h)

    fa14_load_kv(sb + FQ14, K16, V16, b * S_, g, tid);
    CP_COMMIT();
    {   // stage Q (fp16, 128 rows x 256B)
        const __half* src = Q16 + (size_t)t0 * D_ + h * HD_;
        #pragma unroll
        for (int it = 0; it < 8; it++) {
            int idx = it * 256 + tid;
            int row = idx >> 4, ch = idx & 15;
            uint32_t dst = sb + row * 256 + (uint32_t)((ch * 16) ^ ((row & 7) << 4));
            cp_async16(dst, src + (size_t)row * D_ + ch * 8);
        }
        CP_COMMIT();
    }

    float o[16][4];
    #pragma unroll
    for (int f = 0; f < 16; f++)
        #pragma unroll
        for (int r = 0; r < 4; r++) o[f][r] = 0.f;
    float m0 = -1e30f, m1 = -1e30f;
    float lsum0 = 0.f, lsum1 = 0.f;   // full row sums via ones-MMA

    const int r0g = q0 + 16 * wid + (lane >> 2);
    const int c0l = (lane & 3) * 2;

    for (int t = 0; t < nt; t++) {
        CP_WAIT(0);
        __syncthreads();
        if (t + 1 < nt) {
            fa14_load_kv(sb + FQ14 + ((t + 1) & 1) * FST14,
                         K16, V16, b * S_ + (t + 1) * 128, g, tid);
            CP_COMMIT();
        }

        const uint32_t kb  = sb + FQ14 + (t & 1) * FST14;
        const uint32_t vb  = kb + FK14;

        float s[16][4];
        #pragma unroll
        for (int j = 0; j < 16; j++)
            #pragma unroll
            for (int r = 0; r < 4; r++) s[j][r] = 0.f;

        // ---- S = Q K^T (fp16 single pass; log2-domain scores) ----
        #pragma unroll
        for (int kk = 0; kk < 8; kk++) {
            uint32_t qh[4];
            uint32_t qa = sb + qrow * 256 + (uint32_t)(((kk * 32) + lhi16) ^ qswz);
            LDSM4(qh[0], qh[1], qh[2], qh[3], qa);
            #pragma unroll
            for (int np = 0; np < 8; np++) {
                uint32_t ka = kb + (np * 16 + krow_l) * 256 +
                              (uint32_t)(((kk * 32) + kgsel) ^ kswz);
                uint32_t b0, b1, b2, b3;
                LDSM4(b0, b1, b2, b3, ka);
                MMA_F16(s[2*np],   qh, b0, b1);
                MMA_F16(s[2*np+1], qh, b2, b3);
            }
        }

        if (t == qt) {   // diagonal tile: causal mask
            const int k0 = t * 128;
            #pragma unroll
            for (int j = 0; j < 16; j++) {
                int cg = k0 + 8 * j + c0l;
                if (cg     > r0g)     s[j][0] = -1e30f;
                if (cg + 1 > r0g)     s[j][1] = -1e30f;
                if (cg     > r0g + 8) s[j][2] = -1e30f;
                if (cg + 1 > r0g + 8) s[j][3] = -1e30f;
            }
        }

        // ---- online softmax (log2 domain, f16x2 MUFU) ----
        float rm0 = -1e30f, rm1 = -1e30f;
        #pragma unroll
        for (int j = 0; j < 16; j++) {
            rm0 = fmaxf(rm0, fmaxf(s[j][0], s[j][1]));
            rm1 = fmaxf(rm1, fmaxf(s[j][2], s[j][3]));
        }
        rm0 = fmaxf(rm0, __shfl_xor_sync(0xffffffffu, rm0, 1));
        rm0 = fmaxf(rm0, __shfl_xor_sync(0xffffffffu, rm0, 2));
        rm1 = fmaxf(rm1, __shfl_xor_sync(0xffffffffu, rm1, 1));
        rm1 = fmaxf(rm1, __shfl_xor_sync(0xffffffffu, rm1, 2));
        float mn0 = fmaxf(m0, rm0), mn1 = fmaxf(m1, rm1);
        float a0 = ex2f(m0 - mn0), a1 = ex2f(m1 - mn1);
        m0 = mn0; m1 = mn1;

        // p = 2^(s-m) via f16x2 MUFU; result doubles as fp16 PV A-fragment.
        #pragma unroll
        for (int j = 0; j < 16; j++) {
            uint32_t e01 = ex2h2(packf16(s[j][0] - mn0, s[j][1] - mn0));
            uint32_t e23 = ex2h2(packf16(s[j][2] - mn1, s[j][3] - mn1));
            s[j][0] = __uint_as_float(e01);
            s[j][1] = __uint_as_float(e23);
        }

        #pragma unroll
        for (int f = 0; f < 16; f++) {
            o[f][0] *= a0; o[f][1] *= a0;
            o[f][2] *= a1; o[f][3] *= a1;
        }

        // ---- O += P V (fp16) and l += P @ ones (exact row sums) ----
        float lacc[4] = {0.f, 0.f, 0.f, 0.f};
        #pragma unroll
        for (int kk = 0; kk < 8; kk++) {
            uint32_t ah[4];
            ah[0] = __float_as_uint(s[2*kk][0]);
            ah[1] = __float_as_uint(s[2*kk][1]);
            ah[2] = __float_as_uint(s[2*kk+1][0]);
            ah[3] = __float_as_uint(s[2*kk+1][1]);
            MMA_F16(lacc, ah, ONESH2, ONESH2);
            #pragma unroll
            for (int dgp = 0; dgp < 8; dgp++) {
                uint32_t va = vb + (kk * 16 + vrow_l) * 256 +
                              (uint32_t)(((dgp * 32) + vgsel) ^ vswz);
                uint32_t b0, b1, b2, b3;
                LDSM4T(b0, b1, b2, b3, va);
                MMA_F16(o[2*dgp],   ah, b0, b1);
                MMA_F16(o[2*dgp+1], ah, b2, b3);
            }
        }
        lsum0 = lsum0 * a0 + lacc[0];
        lsum1 = lsum1 * a1 + lacc[2];
    }

    // epilogue: lsum is already the full row sum — no reduction needed
    const float inv0 = 1.0f / lsum0;
    const float inv1 = 1.0f / lsum1;
    const int rowg = t0 + 16 * wid + (lane >> 2);
    #pragma unroll
    for (int dg = 0; dg < 16; dg++) {
        int col = h * HD_ + dg * 8 + (lane & 3) * 2;
        *reinterpret_cast<uint32_t*>(Og + (size_t)rowg * D_ + col) =
            packf16(o[dg][0] * inv0, o[dg][1] * inv0);
        *reinterpret_cast<uint32_t*>(Og + (size_t)(rowg + 8) * D_ + col) =
            packf16(o[dg][2] * inv1, o[dg][3] * inv1);
    }
}

// ---------------------------------------------------------------------------
extern "C" void kernel_launch(void* const* d_in, const int* in_sizes, int n_in,
                              void* d_out, int out_size)
{
    const float* x  = (const float*)d_in[0];
    const float* fc = (const float*)d_in[1];
    const float* fs = (const float*)d_in[2];
    const float* wq = (const float*)d_in[3];
    const float* wk = (const float*)d_in[4];
    const float* wv = (const float*)d_in[5];
    const float* wo = (const float*)d_in[6];
    float* out = (float*)d_out;

    __half *x16, *wq16, *wk16, *wv16, *wo16, *attn16, *q16, *k16, *v16;
    cudaGetSymbolAddress((void**)&x16,  g_x16);
    cudaGetSymbolAddress((void**)&wq16, g_wq16);
    cudaGetSymbolAddress((void**)&wk16, g_wk16);
    cudaGetSymbolAddress((void**)&wv16, g_wv16);
    cudaGetSymbolAddress((void**)&wo16, g_wo16);
    cudaGetSymbolAddress((void**)&attn16, g_attn16);
    cudaGetSymbolAddress((void**)&q16, g_q16);
    cudaGetSymbolAddress((void**)&k16, g_k16);
    cudaGetSymbolAddress((void**)&v16, g_v16);

    cudaFuncSetAttribute(gemm_f16,
                         cudaFuncAttributeMaxDynamicSharedMemorySize, GF16_SMEM);
    cudaFuncSetAttribute(flash_v17,
                         cudaFuncAttributeMaxDynamicSharedMemorySize, FA14_SMEM);

    const int n4_xd = T_ * D_ / 4;
    const int n4_w  = D_ * D_ / 4;
    const int n4_kv = KV_ * HD_ * D_ / 4;
    // 1/sqrt(128) * log2(e): flash softmax runs in log2 domain
    const float qscale = 0.08838834764831845f * 1.4426950408889634f;

    to_f16<<<(n4_xd + 255)/256, 256>>>(x,  x16,  n4_xd);
    to_f16<<<(n4_w  + 255)/256, 256>>>(wq, wq16, n4_w);
    to_f16<<<(n4_kv + 255)/256, 256>>>(wk, wk16, n4_kv);
    to_f16<<<(n4_kv + 255)/256, 256>>>(wv, wv16, n4_kv);
    to_f16<<<(n4_w  + 255)/256, 256>>>(wo, wo16, n4_w);

    dim3 blk(256);
    // Q projection: fused rope+scale, fp16 out
    gemm_f16<<<dim3(D_/128, T_/128, 1), blk, GF16_SMEM>>>(
        x16, wq16, wq16, q16, q16, D_, D_, 2, 2, qscale, qscale, fc, fs);
    // fused K+V projections: z=0 K (rope, sc=1), z=1 V (plain fp16)
    gemm_f16<<<dim3((KV_*HD_)/128, T_/128, 2), blk, GF16_SMEM>>>(
        x16, wk16, wv16, k16, v16, KV_*HD_, D_, 2, 1, 1.0f, 1.0f, fc, fs);

    flash_v17<<<dim3(S_/128, H_, B_), blk, FA14_SMEM>>>(q16, k16, v16, attn16);

    // O projection: fp32 out
    gemm_f16<<<dim3(D_/128, T_/128, 1), blk, GF16_SMEM>>>(
        attn16, wo16, wo16, out, out, D_, D_, 0, 0, 1.0f, 1.0f, fc, fs);
}